// round 14
// baseline (speedup 1.0000x reference)
#include <cuda_runtime.h>
#include <math.h>

// Radon transform: img 512x512 f32, angles 180 (int degrees 0..179)
// out[x*180 + a] = sum_y bilinear(img, sy, sx), zero outside image.
//
// Angle pairing: rot_{a+90}[y,x] = rot_a[511-x, y], so one sampling pass of
// rot_a yields projection(a) (column sums) AND projection(a+90) (row sums,
// detector = 511-y). Only angles 0..89 are sampled.

#define NIMG 512
#define NA   180
#define NH   90                    // sampled angle pairs
#define PAD  128
#define PW   768
#define CEN  255.5f
#define FXS  20                    // fixed-point fraction bits
#define FXF  1048576.0f            // 2^20
#define NSPLIT 4                   // y-chunks per detector line

// Quad tables: entry(r,q) = (v[r][q], v[r][q+1], v[r+1][q], v[r+1][q+1])
__device__ float4 g_quad [PW * PW];
__device__ float4 g_quadT[PW * PW];
__device__ float2 g_trig [NH];                     // (cos, sin), angles 0..89
__device__ float  g_part [NIMG * NH * NSPLIT];     // col partials [(x,a)][chunk]
__device__ float  g_rowp [NH * NIMG * 16];         // row partials [a][y][bx]

// Fused builder: one smem img tile serves both quad orientations.
__global__ __launch_bounds__(256) void quad_build_kernel(
    const float* __restrict__ img, const int* __restrict__ angles)
{
    __shared__ float tile[33][36];
    const int tx = threadIdx.x;             // 0..31
    const int ty = threadIdx.y;             // 0..7
    const int lin = ty * 32 + tx;
    const int bx = blockIdx.x * 32;
    const int by = blockIdx.y * 32;

    if (blockIdx.x == 0 && blockIdx.y == 0 && lin < NH) {
        // Match reference precision: deg2rad in f32, then hi-prec sincos.
        float tf = (float)angles[lin] * 0.017453292519943295f;
        double sd, cd;
        sincos((double)tf, &sd, &cd);
        g_trig[lin] = make_float2((float)cd, (float)sd);
    }

    for (int t = lin; t < 33 * 33; t += 256) {
        int i = t / 33;
        int j = t - i * 33;
        int ir = by - PAD + i;
        int iq = bx - PAD + j;
        float v = 0.0f;
        if ((unsigned)ir < NIMG && (unsigned)iq < NIMG)
            v = __ldg(img + ir * NIMG + iq);
        tile[i][j] = v;
    }
    __syncthreads();

    #pragma unroll
    for (int j = 0; j < 32; j += 8) {
        int i = ty + j;
        float v00 = tile[i][tx];
        float v01 = tile[i][tx + 1];
        float v10 = tile[i + 1][tx];
        float v11 = tile[i + 1][tx + 1];
        g_quad[(by + i) * PW + (bx + tx)] = make_float4(v00, v01, v10, v11);
        float w00 = tile[tx][i];
        float w01 = tile[tx + 1][i];
        float w10 = tile[tx][i + 1];
        float w11 = tile[tx + 1][i + 1];
        g_quadT[(bx + i) * PW + (by + tx)] = make_float4(w00, w01, w10, w11);
    }
}

// Main radon kernel (one pass per angle PAIR).
// Block: 128 threads = 4 warps. Warp = 8 detectors x 4 y-phases.
// Grid: (512/32, 90, NSPLIT); each block: 32 detectors x 128-row y-chunk.
__global__ __launch_bounds__(128) void radon_kernel()
{
    __shared__ float s_row[4][128];          // per-warp row sums of this chunk

    const int lane   = threadIdx.x & 31;
    const int warpId = threadIdx.x >> 5;
    const int d      = lane & 7;
    const int yq     = lane >> 3;
    const int x      = blockIdx.x * 32 + warpId * 8 + d;
    const int a      = blockIdx.y;           // 0..89
    const int chunk  = blockIdx.z;

    const float2 cs = g_trig[a];
    const float co = cs.x;
    const float si = cs.y;

    const float xcn = (float)x - CEN;

    // Padded coords at y = chunk*128 + yq, stepping 4 per sample.
    float yc0 = (float)(chunk * 128 + yq) - CEN;
    float R0 = fmaf(-si, xcn, fmaf(co, yc0, CEN + (float)PAD));
    float Q0 = fmaf( co, xcn, fmaf(si, yc0, CEN + (float)PAD));
    float dR = co;
    float dQ = si;
    const float4* base = g_quad;

    // Transpose-swap: contiguous axis gets the larger per-lane step.
    if (fabsf(si) > fabsf(co)) {
        float t0 = R0; R0 = Q0; Q0 = t0;
        float t1 = dR; dR = dQ; dQ = t1;
        base = g_quadT;
    }

    // Fixed-point s11.20 stepping; per-thread y-stride is 4.
    int Rfx = __float2int_rn(R0 * FXF);
    int Qfx = __float2int_rn(Q0 * FXF);
    int dR4 = __float2int_rn(dR * (4.0f * FXF));
    int dQ4 = __float2int_rn(dQ * (4.0f * FXF));

    float acc0 = 0.0f, acc1 = 0.0f;
    float* rowbase = &s_row[warpId][yq];     // + 4*m per sample m

    // 32 samples per thread: 8 batches of 4.
    #pragma unroll 2
    for (int it = 0; it < 8; ++it) {
        int   idxv[4];
        float wrv[4], wqv[4];
        #pragma unroll
        for (int j = 0; j < 4; ++j) {
            int ri = Rfx >> FXS;
            int qi = Qfx >> FXS;
            idxv[j] = ri * PW + qi;
            int wrb = 0x3F800000 | ((Rfx & 0xFFFFF) << 3);
            int wqb = 0x3F800000 | ((Qfx & 0xFFFFF) << 3);
            wrv[j] = __int_as_float(wrb) - 1.0f;
            wqv[j] = __int_as_float(wqb) - 1.0f;
            Rfx += dR4;
            Qfx += dQ4;
        }
        float4 v0 = __ldg(base + idxv[0]);
        float4 v1 = __ldg(base + idxv[1]);
        float4 v2 = __ldg(base + idxv[2]);
        float4 v3 = __ldg(base + idxv[3]);

        float s0, s1, s2, s3;
        {
            float top = fmaf(wqv[0], v0.y - v0.x, v0.x);
            float bot = fmaf(wqv[0], v0.w - v0.z, v0.z);
            s0 = fmaf(wrv[0], bot - top, top);  acc0 += s0;
        }
        {
            float top = fmaf(wqv[1], v1.y - v1.x, v1.x);
            float bot = fmaf(wqv[1], v1.w - v1.z, v1.z);
            s1 = fmaf(wrv[1], bot - top, top);  acc1 += s1;
        }
        {
            float top = fmaf(wqv[2], v2.y - v2.x, v2.x);
            float bot = fmaf(wqv[2], v2.w - v2.z, v2.z);
            s2 = fmaf(wrv[2], bot - top, top);  acc0 += s2;
        }
        {
            float top = fmaf(wqv[3], v3.y - v3.x, v3.x);
            float bot = fmaf(wqv[3], v3.w - v3.z, v3.z);
            s3 = fmaf(wrv[3], bot - top, top);  acc1 += s3;
        }

        // Row sums: reduce each sample over the 8 detector lanes (bits 0..2).
        #pragma unroll
        for (int j = 0; j < 4; ++j) {
            float sj = (j == 0) ? s0 : (j == 1) ? s1 : (j == 2) ? s2 : s3;
            sj += __shfl_xor_sync(0xffffffffu, sj, 1);
            sj += __shfl_xor_sync(0xffffffffu, sj, 2);
            sj += __shfl_xor_sync(0xffffffffu, sj, 4);
            if (d == 0)
                rowbase[4 * (it * 4 + j)] = sj;
        }
    }

    // Column output (angle a): reduce over the 4 y-phases.
    float acc = acc0 + acc1;
    acc += __shfl_xor_sync(0xffffffffu, acc, 16);
    acc += __shfl_xor_sync(0xffffffffu, acc, 8);
    if (lane < 8)
        g_part[(x * NH + a) * NSPLIT + chunk] = acc;

    __syncthreads();

    // Row output partials (angle a+90): combine 4 warp copies per y.
    const int y = threadIdx.x;               // 0..127
    float r = (s_row[0][y] + s_row[1][y]) + (s_row[2][y] + s_row[3][y]);
    g_rowp[(a * NIMG + chunk * 128 + y) * 16 + blockIdx.x] = r;
}

// Final combine: col partials -> out[:, a]; row partials -> out[:, a+90].
__global__ __launch_bounds__(256) void reduce_kernel(float* __restrict__ out)
{
    int i = blockIdx.x * 256 + threadIdx.x;
    if (i >= NIMG * NH) return;
    int x = i / NH;
    int a = i - x * NH;

    float4 p = *reinterpret_cast<const float4*>(g_part + i * NSPLIT);
    out[x * NA + a] = (p.x + p.y) + (p.z + p.w);

    // projection(a+90) at detector x = row sum of rot_a at y = 511 - x.
    const float4* rp = reinterpret_cast<const float4*>(
        g_rowp + (a * NIMG + (NIMG - 1 - x)) * 16);
    float4 q0 = rp[0], q1 = rp[1], q2 = rp[2], q3 = rp[3];
    float s = ((q0.x + q0.y) + (q0.z + q0.w))
            + ((q1.x + q1.y) + (q1.z + q1.w))
            + ((q2.x + q2.y) + (q2.z + q2.w))
            + ((q3.x + q3.y) + (q3.z + q3.w));
    out[x * NA + a + 90] = s;
}

extern "C" void kernel_launch(void* const* d_in, const int* in_sizes, int n_in,
                              void* d_out, int out_size) {
    const float* img    = (const float*)d_in[0];
    const int*   angles = (const int*)d_in[1];
    float*       out    = (float*)d_out;

    dim3 tb(32, 8);
    dim3 tg(PW / 32, PW / 32);
    quad_build_kernel<<<tg, tb>>>(img, angles);

    dim3 rg(NIMG / 32, NH, NSPLIT);
    radon_kernel<<<rg, 128>>>();

    reduce_kernel<<<(NIMG * NH + 255) / 256, 256>>>(out);
}

// round 15
// speedup vs baseline: 1.2127x; 1.2127x over previous
#include <cuda_runtime.h>
#include <math.h>

// Radon transform: img 512x512 f32, angles 180 (int degrees 0..179)
// out[x*180 + a] = sum_y bilinear(img, sy, sx), zero outside image.
//
// Angle pairing: rot_{a+90}[y,x] = rot_a[511-x, y], so one sampling pass of
// rot_a yields projection(a) (column sums) AND projection(a+90) (row sums,
// detector = 511-y). Only angles 0..89 are sampled.

#define NIMG 512
#define NA   180
#define NH   90                    // sampled angle pairs
#define PAD  128
#define PW   768
#define CEN  255.5f
#define FXS  20                    // fixed-point fraction bits
#define FXF  1048576.0f            // 2^20
#define NSPLIT 4                   // y-chunks per detector line

// Quad tables: entry(r,q) = (v[r][q], v[r][q+1], v[r+1][q], v[r+1][q+1])
__device__ float4 g_quad [PW * PW];
__device__ float4 g_quadT[PW * PW];
__device__ float2 g_trig [NH];                     // (cos, sin), angles 0..89
__device__ float  g_part [NIMG * NH * NSPLIT];     // col partials [(x,a)][chunk]
__device__ float  g_rowp [NH * NIMG * 16];         // row partials [a][y][bx]

// Fused builder: one smem img tile serves both quad orientations.
__global__ __launch_bounds__(256) void quad_build_kernel(
    const float* __restrict__ img, const int* __restrict__ angles)
{
    __shared__ float tile[33][36];
    const int tx = threadIdx.x;             // 0..31
    const int ty = threadIdx.y;             // 0..7
    const int lin = ty * 32 + tx;
    const int bx = blockIdx.x * 32;
    const int by = blockIdx.y * 32;

    if (blockIdx.x == 0 && blockIdx.y == 0 && lin < NH) {
        // Match reference precision: deg2rad in f32, then hi-prec sincos.
        float tf = (float)angles[lin] * 0.017453292519943295f;
        double sd, cd;
        sincos((double)tf, &sd, &cd);
        g_trig[lin] = make_float2((float)cd, (float)sd);
    }

    for (int t = lin; t < 33 * 33; t += 256) {
        int i = t / 33;
        int j = t - i * 33;
        int ir = by - PAD + i;
        int iq = bx - PAD + j;
        float v = 0.0f;
        if ((unsigned)ir < NIMG && (unsigned)iq < NIMG)
            v = __ldg(img + ir * NIMG + iq);
        tile[i][j] = v;
    }
    __syncthreads();

    #pragma unroll
    for (int j = 0; j < 32; j += 8) {
        int i = ty + j;
        float v00 = tile[i][tx];
        float v01 = tile[i][tx + 1];
        float v10 = tile[i + 1][tx];
        float v11 = tile[i + 1][tx + 1];
        g_quad[(by + i) * PW + (bx + tx)] = make_float4(v00, v01, v10, v11);
        float w00 = tile[tx][i];
        float w01 = tile[tx + 1][i];
        float w10 = tile[tx][i + 1];
        float w11 = tile[tx + 1][i + 1];
        g_quadT[(bx + i) * PW + (by + tx)] = make_float4(w00, w01, w10, w11);
    }
}

// Main radon kernel (one pass per angle PAIR).
// Block: 128 threads = 4 warps. Warp = 8 detectors x 4 y-phases.
// Grid: (512/32, 90, NSPLIT); each block: 32 detectors x 128-row y-chunk.
__global__ __launch_bounds__(128) void radon_kernel()
{
    __shared__ float s_row[4][128];          // per-warp row sums of this chunk

    const int lane   = threadIdx.x & 31;
    const int warpId = threadIdx.x >> 5;
    const int d      = lane & 7;
    const int yq     = lane >> 3;
    const int x      = blockIdx.x * 32 + warpId * 8 + d;
    const int a      = blockIdx.y;           // 0..89
    const int chunk  = blockIdx.z;

    const float2 cs = g_trig[a];
    const float co = cs.x;
    const float si = cs.y;

    const float xcn = (float)x - CEN;

    // Padded coords at y = chunk*128 + yq, stepping 4 per sample.
    float yc0 = (float)(chunk * 128 + yq) - CEN;
    float R0 = fmaf(-si, xcn, fmaf(co, yc0, CEN + (float)PAD));
    float Q0 = fmaf( co, xcn, fmaf(si, yc0, CEN + (float)PAD));
    float dR = co;
    float dQ = si;
    const float4* base = g_quad;

    // Transpose-swap: contiguous axis gets the larger per-lane step.
    if (fabsf(si) > fabsf(co)) {
        float t0 = R0; R0 = Q0; Q0 = t0;
        float t1 = dR; dR = dQ; dQ = t1;
        base = g_quadT;
    }

    // Fixed-point s11.20 stepping; per-thread y-stride is 4.
    int Rfx = __float2int_rn(R0 * FXF);
    int Qfx = __float2int_rn(Q0 * FXF);
    int dR4 = __float2int_rn(dR * (4.0f * FXF));
    int dQ4 = __float2int_rn(dQ * (4.0f * FXF));

    float acc0 = 0.0f, acc1 = 0.0f;
    float* rowbase = &s_row[warpId][yq];     // + 4*m per sample m

    // 32 samples per thread: 8 batches of 4.
    #pragma unroll 2
    for (int it = 0; it < 8; ++it) {
        int   idxv[4];
        float wrv[4], wqv[4];
        #pragma unroll
        for (int j = 0; j < 4; ++j) {
            int ri = Rfx >> FXS;
            int qi = Qfx >> FXS;
            idxv[j] = ri * PW + qi;
            int wrb = 0x3F800000 | ((Rfx & 0xFFFFF) << 3);
            int wqb = 0x3F800000 | ((Qfx & 0xFFFFF) << 3);
            wrv[j] = __int_as_float(wrb) - 1.0f;
            wqv[j] = __int_as_float(wqb) - 1.0f;
            Rfx += dR4;
            Qfx += dQ4;
        }
        float4 v0 = __ldg(base + idxv[0]);
        float4 v1 = __ldg(base + idxv[1]);
        float4 v2 = __ldg(base + idxv[2]);
        float4 v3 = __ldg(base + idxv[3]);

        float s0, s1, s2, s3;
        {
            float top = fmaf(wqv[0], v0.y - v0.x, v0.x);
            float bot = fmaf(wqv[0], v0.w - v0.z, v0.z);
            s0 = fmaf(wrv[0], bot - top, top);  acc0 += s0;
        }
        {
            float top = fmaf(wqv[1], v1.y - v1.x, v1.x);
            float bot = fmaf(wqv[1], v1.w - v1.z, v1.z);
            s1 = fmaf(wrv[1], bot - top, top);  acc1 += s1;
        }
        {
            float top = fmaf(wqv[2], v2.y - v2.x, v2.x);
            float bot = fmaf(wqv[2], v2.w - v2.z, v2.z);
            s2 = fmaf(wrv[2], bot - top, top);  acc0 += s2;
        }
        {
            float top = fmaf(wqv[3], v3.y - v3.x, v3.x);
            float bot = fmaf(wqv[3], v3.w - v3.z, v3.z);
            s3 = fmaf(wrv[3], bot - top, top);  acc1 += s3;
        }

        // Row sums: reduce each sample over the 8 detector lanes (bits 0..2).
        #pragma unroll
        for (int j = 0; j < 4; ++j) {
            float sj = (j == 0) ? s0 : (j == 1) ? s1 : (j == 2) ? s2 : s3;
            sj += __shfl_xor_sync(0xffffffffu, sj, 1);
            sj += __shfl_xor_sync(0xffffffffu, sj, 2);
            sj += __shfl_xor_sync(0xffffffffu, sj, 4);
            if (d == 0)
                rowbase[4 * (it * 4 + j)] = sj;
        }
    }

    // Column output (angle a): reduce over the 4 y-phases.
    float acc = acc0 + acc1;
    acc += __shfl_xor_sync(0xffffffffu, acc, 16);
    acc += __shfl_xor_sync(0xffffffffu, acc, 8);
    if (lane < 8)
        g_part[(x * NH + a) * NSPLIT + chunk] = acc;

    __syncthreads();

    // Row output partials (angle a+90): combine 4 warp copies per y.
    const int y = threadIdx.x;               // 0..127
    float r = (s_row[0][y] + s_row[1][y]) + (s_row[2][y] + s_row[3][y]);
    g_rowp[(a * NIMG + chunk * 128 + y) * 16 + blockIdx.x] = r;
}

// Final combine: col partials -> out[:, a]; row partials -> out[:, a+90].
__global__ __launch_bounds__(256) void reduce_kernel(float* __restrict__ out)
{
    int i = blockIdx.x * 256 + threadIdx.x;
    if (i >= NIMG * NH) return;
    int x = i / NH;
    int a = i - x * NH;

    float4 p = *reinterpret_cast<const float4*>(g_part + i * NSPLIT);
    out[x * NA + a] = (p.x + p.y) + (p.z + p.w);

    // projection(a+90) at detector x = row sum of rot_a at y = 511 - x.
    const float4* rp = reinterpret_cast<const float4*>(
        g_rowp + (a * NIMG + (NIMG - 1 - x)) * 16);
    float4 q0 = rp[0], q1 = rp[1], q2 = rp[2], q3 = rp[3];
    float s = ((q0.x + q0.y) + (q0.z + q0.w))
            + ((q1.x + q1.y) + (q1.z + q1.w))
            + ((q2.x + q2.y) + (q2.z + q2.w))
            + ((q3.x + q3.y) + (q3.z + q3.w));
    out[x * NA + a + 90] = s;
}

extern "C" void kernel_launch(void* const* d_in, const int* in_sizes, int n_in,
                              void* d_out, int out_size) {
    const float* img    = (const float*)d_in[0];
    const int*   angles = (const int*)d_in[1];
    float*       out    = (float*)d_out;

    dim3 tb(32, 8);
    dim3 tg(PW / 32, PW / 32);
    quad_build_kernel<<<tg, tb>>>(img, angles);

    dim3 rg(NIMG / 32, NH, NSPLIT);
    radon_kernel<<<rg, 128>>>();

    reduce_kernel<<<(NIMG * NH + 255) / 256, 256>>>(out);
}

// round 16
// speedup vs baseline: 1.2199x; 1.0060x over previous
#include <cuda_runtime.h>
#include <math.h>

// Radon transform: img 512x512 f32, angles 180 (int degrees 0..179)
// out[x*180 + a] = sum_y bilinear(img, sy, sx), zero outside image.
//
// Angle pairing: rot_{a+90}[y,x] = rot_a[511-x, y], so one sampling pass of
// rot_a yields projection(a) (column sums) AND projection(a+90) (row sums,
// detector = 511-y). Only angles 0..89 are sampled.

#define NIMG 512
#define NA   180
#define NH   90                    // sampled angle pairs
#define PAD  128
#define PW   768
#define CEN  255.5f
#define FXS  20                    // fixed-point fraction bits
#define FXF  1048576.0f            // 2^20
#define NSPLIT 4                   // y-chunks per detector line

// Quad tables: entry(r,q) = (v[r][q], v[r][q+1], v[r+1][q], v[r+1][q+1])
__device__ float4 g_quad [PW * PW];
__device__ float4 g_quadT[PW * PW];
__device__ float2 g_trig [NH];                     // (cos, sin), angles 0..89
__device__ float  g_part [NIMG * NH * NSPLIT];     // col partials [(x,a)][chunk]
__device__ float  g_rowp [NH * NIMG * 16];         // row partials [a][y][bx]

// Fused builder: one smem img tile serves both quad orientations.
__global__ __launch_bounds__(256) void quad_build_kernel(
    const float* __restrict__ img, const int* __restrict__ angles)
{
    __shared__ float tile[33][36];
    const int tx = threadIdx.x;             // 0..31
    const int ty = threadIdx.y;             // 0..7
    const int lin = ty * 32 + tx;
    const int bx = blockIdx.x * 32;
    const int by = blockIdx.y * 32;

    if (blockIdx.x == 0 && blockIdx.y == 0 && lin < NH) {
        // Match reference precision: deg2rad in f32, then hi-prec sincos.
        float tf = (float)angles[lin] * 0.017453292519943295f;
        double sd, cd;
        sincos((double)tf, &sd, &cd);
        g_trig[lin] = make_float2((float)cd, (float)sd);
    }

    for (int t = lin; t < 33 * 33; t += 256) {
        int i = t / 33;
        int j = t - i * 33;
        int ir = by - PAD + i;
        int iq = bx - PAD + j;
        float v = 0.0f;
        if ((unsigned)ir < NIMG && (unsigned)iq < NIMG)
            v = __ldg(img + ir * NIMG + iq);
        tile[i][j] = v;
    }
    __syncthreads();

    #pragma unroll
    for (int j = 0; j < 32; j += 8) {
        int i = ty + j;
        float v00 = tile[i][tx];
        float v01 = tile[i][tx + 1];
        float v10 = tile[i + 1][tx];
        float v11 = tile[i + 1][tx + 1];
        g_quad[(by + i) * PW + (bx + tx)] = make_float4(v00, v01, v10, v11);
        float w00 = tile[tx][i];
        float w01 = tile[tx + 1][i];
        float w10 = tile[tx][i + 1];
        float w11 = tile[tx + 1][i + 1];
        g_quadT[(bx + i) * PW + (by + tx)] = make_float4(w00, w01, w10, w11);
    }
}

// Main radon kernel (one pass per angle PAIR).
// Block: 128 threads = 4 warps. Warp = 8 detectors x 4 y-phases.
// Grid: (512/32, 90, NSPLIT); each block: 32 detectors x 128-row y-chunk.
__global__ __launch_bounds__(128) void radon_kernel()
{
    __shared__ float s_row[4][128];          // per-warp row sums of this chunk

    const int lane   = threadIdx.x & 31;
    const int warpId = threadIdx.x >> 5;
    const int d      = lane & 7;
    const int yq     = lane >> 3;
    const int x      = blockIdx.x * 32 + warpId * 8 + d;
    const int a      = blockIdx.y;           // 0..89
    const int chunk  = blockIdx.z;

    const float2 cs = g_trig[a];
    const float co = cs.x;
    const float si = cs.y;

    const float xcn = (float)x - CEN;

    // Padded coords at y = chunk*128 + yq, stepping 4 per sample.
    float yc0 = (float)(chunk * 128 + yq) - CEN;
    float R0 = fmaf(-si, xcn, fmaf(co, yc0, CEN + (float)PAD));
    float Q0 = fmaf( co, xcn, fmaf(si, yc0, CEN + (float)PAD));
    float dR = co;
    float dQ = si;
    const float4* base = g_quad;

    // Transpose-swap: contiguous axis gets the larger per-lane step.
    if (fabsf(si) > fabsf(co)) {
        float t0 = R0; R0 = Q0; Q0 = t0;
        float t1 = dR; dR = dQ; dQ = t1;
        base = g_quadT;
    }

    // Fixed-point s11.20 stepping; per-thread y-stride is 4.
    int Rfx = __float2int_rn(R0 * FXF);
    int Qfx = __float2int_rn(Q0 * FXF);
    int dR4 = __float2int_rn(dR * (4.0f * FXF));
    int dQ4 = __float2int_rn(dQ * (4.0f * FXF));

    float acc0 = 0.0f, acc1 = 0.0f;
    float* rowbase = &s_row[warpId][yq];     // + 4*m per sample m

    // 32 samples per thread: 8 batches of 4.
    #pragma unroll 2
    for (int it = 0; it < 8; ++it) {
        int   idxv[4];
        float wrv[4], wqv[4];
        #pragma unroll
        for (int j = 0; j < 4; ++j) {
            int ri = Rfx >> FXS;
            int qi = Qfx >> FXS;
            idxv[j] = ri * PW + qi;
            int wrb = 0x3F800000 | ((Rfx & 0xFFFFF) << 3);
            int wqb = 0x3F800000 | ((Qfx & 0xFFFFF) << 3);
            wrv[j] = __int_as_float(wrb) - 1.0f;
            wqv[j] = __int_as_float(wqb) - 1.0f;
            Rfx += dR4;
            Qfx += dQ4;
        }
        float4 v0 = __ldg(base + idxv[0]);
        float4 v1 = __ldg(base + idxv[1]);
        float4 v2 = __ldg(base + idxv[2]);
        float4 v3 = __ldg(base + idxv[3]);

        float s0, s1, s2, s3;
        {
            float top = fmaf(wqv[0], v0.y - v0.x, v0.x);
            float bot = fmaf(wqv[0], v0.w - v0.z, v0.z);
            s0 = fmaf(wrv[0], bot - top, top);  acc0 += s0;
        }
        {
            float top = fmaf(wqv[1], v1.y - v1.x, v1.x);
            float bot = fmaf(wqv[1], v1.w - v1.z, v1.z);
            s1 = fmaf(wrv[1], bot - top, top);  acc1 += s1;
        }
        {
            float top = fmaf(wqv[2], v2.y - v2.x, v2.x);
            float bot = fmaf(wqv[2], v2.w - v2.z, v2.z);
            s2 = fmaf(wrv[2], bot - top, top);  acc0 += s2;
        }
        {
            float top = fmaf(wqv[3], v3.y - v3.x, v3.x);
            float bot = fmaf(wqv[3], v3.w - v3.z, v3.z);
            s3 = fmaf(wrv[3], bot - top, top);  acc1 += s3;
        }

        // Row sums: reduce each sample over the 8 detector lanes (bits 0..2).
        #pragma unroll
        for (int j = 0; j < 4; ++j) {
            float sj = (j == 0) ? s0 : (j == 1) ? s1 : (j == 2) ? s2 : s3;
            sj += __shfl_xor_sync(0xffffffffu, sj, 1);
            sj += __shfl_xor_sync(0xffffffffu, sj, 2);
            sj += __shfl_xor_sync(0xffffffffu, sj, 4);
            if (d == 0)
                rowbase[4 * (it * 4 + j)] = sj;
        }
    }

    // Column output (angle a): reduce over the 4 y-phases.
    float acc = acc0 + acc1;
    acc += __shfl_xor_sync(0xffffffffu, acc, 16);
    acc += __shfl_xor_sync(0xffffffffu, acc, 8);
    if (lane < 8)
        g_part[(x * NH + a) * NSPLIT + chunk] = acc;

    __syncthreads();

    // Row output partials (angle a+90): combine 4 warp copies per y.
    const int y = threadIdx.x;               // 0..127
    float r = (s_row[0][y] + s_row[1][y]) + (s_row[2][y] + s_row[3][y]);
    g_rowp[(a * NIMG + chunk * 128 + y) * 16 + blockIdx.x] = r;
}

// Final combine: col partials -> out[:, a]; row partials -> out[:, a+90].
__global__ __launch_bounds__(256) void reduce_kernel(float* __restrict__ out)
{
    int i = blockIdx.x * 256 + threadIdx.x;
    if (i >= NIMG * NH) return;
    int x = i / NH;
    int a = i - x * NH;

    float4 p = *reinterpret_cast<const float4*>(g_part + i * NSPLIT);
    out[x * NA + a] = (p.x + p.y) + (p.z + p.w);

    // projection(a+90) at detector x = row sum of rot_a at y = 511 - x.
    const float4* rp = reinterpret_cast<const float4*>(
        g_rowp + (a * NIMG + (NIMG - 1 - x)) * 16);
    float4 q0 = rp[0], q1 = rp[1], q2 = rp[2], q3 = rp[3];
    float s = ((q0.x + q0.y) + (q0.z + q0.w))
            + ((q1.x + q1.y) + (q1.z + q1.w))
            + ((q2.x + q2.y) + (q2.z + q2.w))
            + ((q3.x + q3.y) + (q3.z + q3.w));
    out[x * NA + a + 90] = s;
}

extern "C" void kernel_launch(void* const* d_in, const int* in_sizes, int n_in,
                              void* d_out, int out_size) {
    const float* img    = (const float*)d_in[0];
    const int*   angles = (const int*)d_in[1];
    float*       out    = (float*)d_out;

    dim3 tb(32, 8);
    dim3 tg(PW / 32, PW / 32);
    quad_build_kernel<<<tg, tb>>>(img, angles);

    dim3 rg(NIMG / 32, NH, NSPLIT);
    radon_kernel<<<rg, 128>>>();

    reduce_kernel<<<(NIMG * NH + 255) / 256, 256>>>(out);
}